// round 11
// baseline (speedup 1.0000x reference)
#include <cuda_runtime.h>
#include <cstdint>

typedef unsigned long long ull;
#define FULLM 0xffffffffu

#define NQ 8
#define DIM 256
#define NW 16
#define NB 16
#define NROTS 64
#define EMB 512
#define NVOCAB 50257
#define NOUT_OP (NB*NVOCAB)

// ---------------- scratch ----------------
__device__ float g_fp[NB];
__device__ __align__(16) float g_h[NB*EMB];   // h[b][k]

// ---------------- f32x2 helpers ----------------
__device__ __forceinline__ ull pack2(float a, float b){
    ull r; asm("mov.b64 %0, {%1,%2};" : "=l"(r) : "f"(a), "f"(b)); return r;
}
__device__ __forceinline__ void unpack2(ull v, float &a, float &b){
    asm("mov.b64 {%0,%1}, %2;" : "=f"(a), "=f"(b) : "l"(v));
}
__device__ __forceinline__ void fma2(ull &d, ull a, ull b){
    asm("fma.rn.f32x2 %0, %1, %2, %0;" : "+l"(d) : "l"(a), "l"(b));
}
__device__ __forceinline__ ull add2(ull a, ull b){
    ull r; asm("add.rn.f32x2 %0, %1, %2;" : "=l"(r) : "l"(a), "l"(b)); return r;
}

// =====================================================================
// Warp-resident quantum gates. amp index a = lane*8 + r
// =====================================================================
template<int P>
__device__ __forceinline__ void ry_gate(float2* s, float c, float sn, int lane){
    if constexpr (P < 3){
        #pragma unroll
        for (int r = 0; r < 8; r++)
            if (!(r & (1<<P))){
                const int r1 = r | (1<<P);
                float2 a0 = s[r], a1 = s[r1];
                s[r]  = make_float2(c*a0.x - sn*a1.x, c*a0.y - sn*a1.y);
                s[r1] = make_float2(sn*a0.x + c*a1.x, sn*a0.y + c*a1.y);
            }
    } else {
        const int M = 1 << (P-3);
        float sg = (lane & M) ? sn : -sn;
        #pragma unroll
        for (int r = 0; r < 8; r++){
            float px = __shfl_xor_sync(FULLM, s[r].x, M);
            float py = __shfl_xor_sync(FULLM, s[r].y, M);
            s[r] = make_float2(c*s[r].x + sg*px, c*s[r].y + sg*py);
        }
    }
}

template<int PC, int PT>
__device__ __forceinline__ void crx_gate(float2* s, float c, float sn, int lane){
    if constexpr (PT < 3 && PC < 3){
        #pragma unroll
        for (int r = 0; r < 8; r++)
            if ((r & (1<<PC)) && !(r & (1<<PT))){
                const int r1 = r | (1<<PT);
                float2 a0 = s[r], a1 = s[r1];
                s[r]  = make_float2(c*a0.x + sn*a1.y, c*a0.y - sn*a1.x);
                s[r1] = make_float2(c*a1.x + sn*a0.y, c*a1.y - sn*a0.x);
            }
    } else if constexpr (PT < 3 && PC >= 3){
        if (lane & (1 << (PC-3))){
            #pragma unroll
            for (int r = 0; r < 8; r++)
                if (!(r & (1<<PT))){
                    const int r1 = r | (1<<PT);
                    float2 a0 = s[r], a1 = s[r1];
                    s[r]  = make_float2(c*a0.x + sn*a1.y, c*a0.y - sn*a1.x);
                    s[r1] = make_float2(c*a1.x + sn*a0.y, c*a1.y - sn*a0.x);
                }
        }
    } else if constexpr (PT >= 3 && PC < 3){
        const int M = 1 << (PT-3);
        #pragma unroll
        for (int r = 0; r < 8; r++){
            float px = __shfl_xor_sync(FULLM, s[r].x, M);
            float py = __shfl_xor_sync(FULLM, s[r].y, M);
            if (r & (1<<PC))
                s[r] = make_float2(c*s[r].x + sn*py, c*s[r].y - sn*px);
        }
    } else {
        const int M = 1 << (PT-3);
        bool ctl = (lane & (1 << (PC-3))) != 0;
        #pragma unroll
        for (int r = 0; r < 8; r++){
            float px = __shfl_xor_sync(FULLM, s[r].x, M);
            float py = __shfl_xor_sync(FULLM, s[r].y, M);
            if (ctl)
                s[r] = make_float2(c*s[r].x + sn*py, c*s[r].y - sn*px);
        }
    }
}

__device__ __forceinline__ void layer(float2* s, const float2* ang, int lane){
    float2 a;
    #define RYG(P, I)     { a = ang[I]; ry_gate<P>(s, a.x, a.y, lane); }
    #define CRXG(PC,PT,I) { a = ang[I]; crx_gate<PC,PT>(s, a.x, a.y, lane); }
    RYG(7,0) RYG(6,1) RYG(5,2) RYG(4,3) RYG(3,4) RYG(2,5) RYG(1,6) RYG(0,7)
    CRXG(0,7,8) CRXG(1,0,9) CRXG(2,1,10) CRXG(3,2,11)
    CRXG(4,3,12) CRXG(5,4,13) CRXG(6,5,14) CRXG(7,6,15)
    RYG(7,16) RYG(6,17) RYG(5,18) RYG(4,19) RYG(3,20) RYG(2,21) RYG(1,22) RYG(0,23)
    CRXG(0,1,24) CRXG(7,0,25) CRXG(6,7,26) CRXG(5,6,27)
    CRXG(4,5,28) CRXG(3,4,29) CRXG(2,3,30) CRXG(1,2,31)
    #undef RYG
    #undef CRXG
}

// =====================================================================
// Kernel 1: EVERYTHING except FF2. 16 blocks x 512 thr. (unchanged, known-good)
// =====================================================================
union MidU {
    float2 embp[8][EMB];
    float2 st[NW][DIM];
};

__global__ void __launch_bounds__(512) mid_kernel(const int* __restrict__ x,
                           const float* __restrict__ embW,
                           const float* __restrict__ e2rW,
                           const float* __restrict__ e2rb,
                           const float* __restrict__ mix,
                           const float* __restrict__ poly,
                           const float* __restrict__ qff,
                           const float* __restrict__ ff1W,
                           const float* __restrict__ ff1b){
    __shared__ MidU u;
    __shared__ float2 sh_ang[NW][NROTS];
    __shared__ float2 sh_comb[DIM];
    __shared__ float2 sh_cf[NW];
    __shared__ float2 sh_qang[32];
    __shared__ float  redv[16];
    __shared__ float  red3[12];
    __shared__ float  exps[24];
    __shared__ float  sh_inv;

    int b = blockIdx.x;
    int t = threadIdx.x;
    int w = t >> 5, lane = t & 31;

    {
        float* embf = (float*)u.embp;
        for (int idx = t; idx < NW*EMB; idx += 512){
            int w_ = idx >> 9, k = idx & 511;
            float val = embW[(size_t)x[b*NW + w_]*EMB + k];
            embf[((w_ >> 1)*EMB + k)*2 + (w_ & 1)] = val;
        }
    }
    if (t < 32){
        float re = 0.f, im = 0.f, a = 0.f;
        if (t < NW){ re = mix[2*t]; im = mix[2*t+1]; a = sqrtf(re*re + im*im); }
        float s = a;
        #pragma unroll
        for (int o = 16; o; o >>= 1) s += __shfl_xor_sync(FULLM, s, o);
        float inv = 1.f / fmaxf(s, 1e-12f);
        if (t < NW) sh_cf[t] = make_float2(re*inv, im*inv);
    }
    if (t >= 32 && t < 64){
        int i = t - 32;
        float sv, cv; sincosf(qff[i]*0.5f, &sv, &cv);
        sh_qang[i] = make_float2(cv, sv);
    }
    __syncthreads();

    {
        ull acc2[4][8];
        #pragma unroll
        for (int rr = 0; rr < 4; rr++)
            #pragma unroll
            for (int wp = 0; wp < 8; wp++) acc2[rr][wp] = 0ULL;

        #pragma unroll 4
        for (int it = 0; it < 16; it++){
            int k = it*32 + lane;
            float wr_[4];
            #pragma unroll
            for (int rr = 0; rr < 4; rr++)
                wr_[rr] = e2rW[(size_t)(w*4 + rr)*EMB + k];
            ull e2[8];
            #pragma unroll
            for (int wp = 0; wp < 8; wp++)
                e2[wp] = *(const ull*)&u.embp[wp][k];
            #pragma unroll
            for (int rr = 0; rr < 4; rr++){
                ull w2 = pack2(wr_[rr], wr_[rr]);
                #pragma unroll
                for (int wp = 0; wp < 8; wp++)
                    fma2(acc2[rr][wp], w2, e2[wp]);
            }
        }
        #pragma unroll
        for (int o = 16; o; o >>= 1)
            #pragma unroll
            for (int rr = 0; rr < 4; rr++)
                #pragma unroll
                for (int wp = 0; wp < 8; wp++)
                    acc2[rr][wp] = add2(acc2[rr][wp], __shfl_xor_sync(FULLM, acc2[rr][wp], o));
        int lrr = lane >> 3, lwp = lane & 7;
        ull v = 0ULL;
        #pragma unroll
        for (int rr = 0; rr < 4; rr++)
            #pragma unroll
            for (int wp = 0; wp < 8; wp++)
                if (rr == lrr && wp == lwp) v = acc2[rr][wp];
        int r = w*4 + lrr;
        float bias_r = e2rb[r];
        float lo, hi; unpack2(v, lo, hi);
        float s0, c0, s1, c1;
        sincosf((lo + bias_r)*0.5f, &s0, &c0);
        sincosf((hi + bias_r)*0.5f, &s1, &c1);
        sh_ang[2*lwp][r]     = make_float2(c0, s0);
        sh_ang[2*lwp + 1][r] = make_float2(c1, s1);
    }
    __syncthreads();

    float2 pacc = make_float2((t == 0) ? poly[0] : 0.f, 0.f);

    #pragma unroll 1
    for (int d = 1; d <= 3; d++){
        float2 s[8];
        if (d == 1){
            #pragma unroll
            for (int r = 0; r < 8; r++)
                s[r] = make_float2((lane == 0 && r == 0) ? 1.f : 0.f, 0.f);
        } else {
            #pragma unroll
            for (int r = 0; r < 8; r++) s[r] = sh_comb[lane*8 + r];
        }
        #pragma unroll 1
        for (int l = 0; l < 2; l++)
            layer(s, &sh_ang[w][32*l], lane);
        #pragma unroll
        for (int r = 0; r < 8; r++) u.st[w][lane*8 + r] = s[r];
        __syncthreads();
        if (t < DIM){
            float2 acc2 = make_float2(0.f, 0.f);
            #pragma unroll
            for (int ww = 0; ww < NW; ww++){
                float2 c = sh_cf[ww];
                float2 v = u.st[ww][t];
                acc2.x += c.x*v.x - c.y*v.y;
                acc2.y += c.x*v.y + c.y*v.x;
            }
            float pd = poly[d];
            pacc.x += pd*acc2.x; pacc.y += pd*acc2.y;
            sh_comb[t] = acc2;
        }
        __syncthreads();
    }

    float psum = fabsf(poly[0]) + fabsf(poly[1]) + fabsf(poly[2]) + fabsf(poly[3]);
    float invp = 1.f / psum;
    float2 m = make_float2(pacc.x*invp, pacc.y*invp);
    if (t < DIM){
        float loc = m.x*m.x + m.y*m.y;
        #pragma unroll
        for (int o = 16; o; o >>= 1) loc += __shfl_xor_sync(FULLM, loc, o);
        if (lane == 0) redv[w] = loc;
    }
    __syncthreads();
    if (t == 0){
        float fp = sqrtf(redv[0]+redv[1]+redv[2]+redv[3]+redv[4]+redv[5]+redv[6]+redv[7]);
        g_fp[b] = fp;
        sh_inv = 1.f / fmaxf(fp, 1e-12f);
    }
    __syncthreads();
    if (t < DIM) sh_comb[t] = make_float2(m.x*sh_inv, m.y*sh_inv);
    __syncthreads();

    if (w == 0){
        float2 s[8];
        #pragma unroll
        for (int r = 0; r < 8; r++) s[r] = sh_comb[lane*8 + r];
        layer(s, sh_qang, lane);
        #pragma unroll
        for (int r = 0; r < 8; r++) sh_comb[lane*8 + r] = s[r];
    }
    __syncthreads();

    for (int wq = 0; wq < 8; wq++){
        int p = 7 - wq;
        if (t < 128){
            int i0 = ((t >> p) << (p+1)) | (t & ((1 << p) - 1));
            int i1 = i0 | (1 << p);
            float2 a0 = sh_comb[i0], a1 = sh_comb[i1];
            float cr = a0.x*a1.x + a0.y*a1.y;
            float ci = a0.x*a1.y - a0.y*a1.x;
            float zz = (a0.x*a0.x + a0.y*a0.y) - (a1.x*a1.x + a1.y*a1.y);
            #pragma unroll
            for (int o = 16; o; o >>= 1){
                cr += __shfl_xor_sync(FULLM, cr, o);
                ci += __shfl_xor_sync(FULLM, ci, o);
                zz += __shfl_xor_sync(FULLM, zz, o);
            }
            if (lane == 0){ red3[w*3] = cr; red3[w*3+1] = ci; red3[w*3+2] = zz; }
        }
        __syncthreads();
        if (t == 0){
            exps[wq]      = 2.f*(red3[0] + red3[3] + red3[6] + red3[9]);
            exps[8 + wq]  = 2.f*(red3[1] + red3[4] + red3[7] + red3[10]);
            exps[16 + wq] =      red3[2] + red3[5] + red3[8] + red3[11];
        }
        __syncthreads();
    }

    {
        float a = ff1b[t];
        const float* wr = ff1W + t*24;
        #pragma unroll
        for (int m2 = 0; m2 < 24; m2++) a += exps[m2] * wr[m2];
        g_h[b*EMB + t] = fmaxf(a, 0.f);
    }
}

// =====================================================================
// Kernel 2: FF2. k-paired f32x2. 512 thr = 16 warps (4 vgrp x 4 bgrp).
// Thread tile 8v x 4b; block tile 32v x 16b. acc = (even-k, odd-k) pairs.
// =====================================================================
union FF2U {
    float  hp[NB][EMB];       // 32 KB during mainloop
    float  red[512*9];        // 18 KB during reduction (after mainloop)
};

__global__ void __launch_bounds__(512) ff2_kernel(const float* __restrict__ W,
                                                  const float* __restrict__ bias,
                                                  float* __restrict__ out,
                                                  int write_scalar){
    __shared__ FF2U u;
    int t = threadIdx.x;
    int wid = t >> 5, lane = t & 31;

    // stage h: straight float4 copy
    {
        const float4* src = (const float4*)g_h;
        float4* dst = (float4*)u.hp;
        #pragma unroll
        for (int i = 0; i < 4; i++)
            dst[t + i*512] = src[t + i*512];
    }
    if (write_scalar && blockIdx.x == 0 && t == 0){
        float s = 0.f;
        #pragma unroll
        for (int b = 0; b < NB; b++) s += g_fp[b];
        out[NOUT_OP] = s * (1.f/16.f);
    }
    __syncthreads();

    int vgrp = wid >> 2, bgrp = wid & 3;
    int vbase = blockIdx.x*32 + vgrp*8;

    ull acc[8][4];
    #pragma unroll
    for (int vi = 0; vi < 8; vi++)
        #pragma unroll
        for (int bi = 0; bi < 4; bi++) acc[vi][bi] = 0ULL;

    // per-row byte offsets (uint32, clamped) — low reg pressure
    unsigned woff[8];
    #pragma unroll
    for (int vi = 0; vi < 8; vi++){
        int v = vbase + vi; if (v > NVOCAB-1) v = NVOCAB-1;
        woff[vi] = (unsigned)v * (EMB*4);
    }
    const char* wb = (const char*)W;

    #pragma unroll
    for (int it = 0; it < 4; it++){
        int kb = (it*32 + lane)*16;     // byte offset within row
        ulonglong2 wl[8];
        #pragma unroll
        for (int vi = 0; vi < 8; vi++)
            wl[vi] = *(const ulonglong2*)(wb + woff[vi] + kb);
        ulonglong2 hl[4];
        #pragma unroll
        for (int bi = 0; bi < 4; bi++)
            hl[bi] = *(const ulonglong2*)&u.hp[bgrp*4 + bi][(it*32 + lane)*4];
        #pragma unroll
        for (int vi = 0; vi < 8; vi++){
            #pragma unroll
            for (int bi = 0; bi < 4; bi++){
                fma2(acc[vi][bi], wl[vi].x, hl[bi].x);
                fma2(acc[vi][bi], wl[vi].y, hl[bi].y);
            }
        }
    }
    __syncthreads();   // hp dead

    // 4 rounds: round r reduces vi = {2r, 2r+1}
    #pragma unroll 1
    for (int r = 0; r < 4; r++){
        #pragma unroll
        for (int vi2 = 0; vi2 < 2; vi2++)
            #pragma unroll
            for (int bi = 0; bi < 4; bi++){
                float lo, hi; unpack2(acc[2*r + vi2][bi], lo, hi);
                u.red[t*9 + vi2*4 + bi] = lo + hi;
            }
        __syncthreads();
        if (t < 128){
            int vg = t >> 5, vi2 = (t >> 4) & 1, b_ = t & 15;
            int wsrc = vg*4 + (b_ >> 2);
            int idx  = vi2*4 + (b_ & 3);
            float sum = 0.f;
            #pragma unroll
            for (int ln = 0; ln < 32; ln++)
                sum += u.red[(wsrc*32 + ln)*9 + idx];
            int v = blockIdx.x*32 + vg*8 + 2*r + vi2;
            if (v < NVOCAB)
                out[(size_t)b_*NVOCAB + v] = sum + bias[v];
        }
        __syncthreads();
    }
}

// ---------------- launch ----------------
extern "C" void kernel_launch(void* const* d_in, const int* in_sizes, int n_in,
                              void* d_out, int out_size){
    const int*   x    = (const int*)  d_in[0];
    const float* embW = (const float*)d_in[1];
    const float* e2rW = (const float*)d_in[2];
    const float* e2rb = (const float*)d_in[3];
    const float* poly = (const float*)d_in[4];
    const float* mix  = (const float*)d_in[5];
    const float* qff  = (const float*)d_in[6];
    const float* ff1W = (const float*)d_in[7];
    const float* ff1b = (const float*)d_in[8];
    const float* ff2W = (const float*)d_in[9];
    const float* ff2b = (const float*)d_in[10];
    float* out = (float*)d_out;

    mid_kernel<<<NB, 512>>>(x, embW, e2rW, e2rb, mix, poly, qff, ff1W, ff1b);

    int ws = (out_size > NOUT_OP) ? 1 : 0;
    ff2_kernel<<<(NVOCAB + 31)/32, 512>>>(ff2W, ff2b, out, ws);
}

// round 15
// speedup vs baseline: 1.7683x; 1.7683x over previous
#include <cuda_runtime.h>
#include <cstdint>

typedef unsigned long long ull;
#define FULLM 0xffffffffu

#define NQ 8
#define DIM 256
#define NW 16
#define NB 16
#define NROTS 64
#define EMB 512
#define NVOCAB 50257
#define NOUT_OP (NB*NVOCAB)

// ---------------- scratch ----------------
__device__ float g_fp[NB];
__device__ __align__(16) float g_h[NB*EMB];   // h[b][k]

// ---------------- f32x2 helpers ----------------
__device__ __forceinline__ ull pack2(float a, float b){
    ull r; asm("mov.b64 %0, {%1,%2};" : "=l"(r) : "f"(a), "f"(b)); return r;
}
__device__ __forceinline__ void unpack2(ull v, float &a, float &b){
    asm("mov.b64 {%0,%1}, %2;" : "=f"(a), "=f"(b) : "l"(v));
}
__device__ __forceinline__ void fma2(ull &d, ull a, ull b){
    asm("fma.rn.f32x2 %0, %1, %2, %0;" : "+l"(d) : "l"(a), "l"(b));
}
__device__ __forceinline__ ull add2(ull a, ull b){
    ull r; asm("add.rn.f32x2 %0, %1, %2;" : "=l"(r) : "l"(a), "l"(b)); return r;
}

// ---------------- tf32 mma helpers ----------------
__device__ __forceinline__ float tf32c(float f){
    uint32_t u; asm("cvt.rna.tf32.f32 %0, %1;" : "=r"(u) : "f"(f));
    return __uint_as_float(u);
}
// operands {a0,a1,a2,a3} = {A0.x, A1.x, A0.y, A1.y}; B = {b0,b1}
__device__ __forceinline__ void mma8(float* d, uint2 A0, uint2 A1, uint2 B){
    asm volatile("mma.sync.aligned.m16n8k8.row.col.f32.tf32.tf32.f32 "
        "{%0,%1,%2,%3}, {%4,%5,%6,%7}, {%8,%9}, {%0,%1,%2,%3};"
        : "+f"(d[0]), "+f"(d[1]), "+f"(d[2]), "+f"(d[3])
        : "r"(A0.x), "r"(A1.x), "r"(A0.y), "r"(A1.y), "r"(B.x), "r"(B.y));
}

// =====================================================================
// Warp-resident quantum gates. amp index a = lane*8 + r
// =====================================================================
template<int P>
__device__ __forceinline__ void ry_gate(float2* s, float c, float sn, int lane){
    if constexpr (P < 3){
        #pragma unroll
        for (int r = 0; r < 8; r++)
            if (!(r & (1<<P))){
                const int r1 = r | (1<<P);
                float2 a0 = s[r], a1 = s[r1];
                s[r]  = make_float2(c*a0.x - sn*a1.x, c*a0.y - sn*a1.y);
                s[r1] = make_float2(sn*a0.x + c*a1.x, sn*a0.y + c*a1.y);
            }
    } else {
        const int M = 1 << (P-3);
        float sg = (lane & M) ? sn : -sn;
        #pragma unroll
        for (int r = 0; r < 8; r++){
            float px = __shfl_xor_sync(FULLM, s[r].x, M);
            float py = __shfl_xor_sync(FULLM, s[r].y, M);
            s[r] = make_float2(c*s[r].x + sg*px, c*s[r].y + sg*py);
        }
    }
}

template<int PC, int PT>
__device__ __forceinline__ void crx_gate(float2* s, float c, float sn, int lane){
    if constexpr (PT < 3 && PC < 3){
        #pragma unroll
        for (int r = 0; r < 8; r++)
            if ((r & (1<<PC)) && !(r & (1<<PT))){
                const int r1 = r | (1<<PT);
                float2 a0 = s[r], a1 = s[r1];
                s[r]  = make_float2(c*a0.x + sn*a1.y, c*a0.y - sn*a1.x);
                s[r1] = make_float2(c*a1.x + sn*a0.y, c*a1.y - sn*a0.x);
            }
    } else if constexpr (PT < 3 && PC >= 3){
        if (lane & (1 << (PC-3))){
            #pragma unroll
            for (int r = 0; r < 8; r++)
                if (!(r & (1<<PT))){
                    const int r1 = r | (1<<PT);
                    float2 a0 = s[r], a1 = s[r1];
                    s[r]  = make_float2(c*a0.x + sn*a1.y, c*a0.y - sn*a1.x);
                    s[r1] = make_float2(c*a1.x + sn*a0.y, c*a1.y - sn*a0.x);
                }
        }
    } else if constexpr (PT >= 3 && PC < 3){
        const int M = 1 << (PT-3);
        #pragma unroll
        for (int r = 0; r < 8; r++){
            float px = __shfl_xor_sync(FULLM, s[r].x, M);
            float py = __shfl_xor_sync(FULLM, s[r].y, M);
            if (r & (1<<PC))
                s[r] = make_float2(c*s[r].x + sn*py, c*s[r].y - sn*px);
        }
    } else {
        const int M = 1 << (PT-3);
        bool ctl = (lane & (1 << (PC-3))) != 0;
        #pragma unroll
        for (int r = 0; r < 8; r++){
            float px = __shfl_xor_sync(FULLM, s[r].x, M);
            float py = __shfl_xor_sync(FULLM, s[r].y, M);
            if (ctl)
                s[r] = make_float2(c*s[r].x + sn*py, c*s[r].y - sn*px);
        }
    }
}

__device__ __forceinline__ void layer(float2* s, const float2* ang, int lane){
    float2 a;
    #define RYG(P, I)     { a = ang[I]; ry_gate<P>(s, a.x, a.y, lane); }
    #define CRXG(PC,PT,I) { a = ang[I]; crx_gate<PC,PT>(s, a.x, a.y, lane); }
    RYG(7,0) RYG(6,1) RYG(5,2) RYG(4,3) RYG(3,4) RYG(2,5) RYG(1,6) RYG(0,7)
    CRXG(0,7,8) CRXG(1,0,9) CRXG(2,1,10) CRXG(3,2,11)
    CRXG(4,3,12) CRXG(5,4,13) CRXG(6,5,14) CRXG(7,6,15)
    RYG(7,16) RYG(6,17) RYG(5,18) RYG(4,19) RYG(3,20) RYG(2,21) RYG(1,22) RYG(0,23)
    CRXG(0,1,24) CRXG(7,0,25) CRXG(6,7,26) CRXG(5,6,27)
    CRXG(4,5,28) CRXG(3,4,29) CRXG(2,3,30) CRXG(1,2,31)
    #undef RYG
    #undef CRXG
}

// =====================================================================
// Kernel 1: EVERYTHING except FF2. 16 blocks x 512 thr. (unchanged, known-good)
// =====================================================================
union MidU {
    float2 embp[8][EMB];
    float2 st[NW][DIM];
};

__global__ void __launch_bounds__(512) mid_kernel(const int* __restrict__ x,
                           const float* __restrict__ embW,
                           const float* __restrict__ e2rW,
                           const float* __restrict__ e2rb,
                           const float* __restrict__ mix,
                           const float* __restrict__ poly,
                           const float* __restrict__ qff,
                           const float* __restrict__ ff1W,
                           const float* __restrict__ ff1b){
    __shared__ MidU u;
    __shared__ float2 sh_ang[NW][NROTS];
    __shared__ float2 sh_comb[DIM];
    __shared__ float2 sh_cf[NW];
    __shared__ float2 sh_qang[32];
    __shared__ float  redv[16];
    __shared__ float  red3[12];
    __shared__ float  exps[24];
    __shared__ float  sh_inv;

    int b = blockIdx.x;
    int t = threadIdx.x;
    int w = t >> 5, lane = t & 31;

    {
        float* embf = (float*)u.embp;
        for (int idx = t; idx < NW*EMB; idx += 512){
            int w_ = idx >> 9, k = idx & 511;
            float val = embW[(size_t)x[b*NW + w_]*EMB + k];
            embf[((w_ >> 1)*EMB + k)*2 + (w_ & 1)] = val;
        }
    }
    if (t < 32){
        float re = 0.f, im = 0.f, a = 0.f;
        if (t < NW){ re = mix[2*t]; im = mix[2*t+1]; a = sqrtf(re*re + im*im); }
        float s = a;
        #pragma unroll
        for (int o = 16; o; o >>= 1) s += __shfl_xor_sync(FULLM, s, o);
        float inv = 1.f / fmaxf(s, 1e-12f);
        if (t < NW) sh_cf[t] = make_float2(re*inv, im*inv);
    }
    if (t >= 32 && t < 64){
        int i = t - 32;
        float sv, cv; sincosf(qff[i]*0.5f, &sv, &cv);
        sh_qang[i] = make_float2(cv, sv);
    }
    __syncthreads();

    {
        ull acc2[4][8];
        #pragma unroll
        for (int rr = 0; rr < 4; rr++)
            #pragma unroll
            for (int wp = 0; wp < 8; wp++) acc2[rr][wp] = 0ULL;

        #pragma unroll 4
        for (int it = 0; it < 16; it++){
            int k = it*32 + lane;
            float wr_[4];
            #pragma unroll
            for (int rr = 0; rr < 4; rr++)
                wr_[rr] = e2rW[(size_t)(w*4 + rr)*EMB + k];
            ull e2[8];
            #pragma unroll
            for (int wp = 0; wp < 8; wp++)
                e2[wp] = *(const ull*)&u.embp[wp][k];
            #pragma unroll
            for (int rr = 0; rr < 4; rr++){
                ull w2 = pack2(wr_[rr], wr_[rr]);
                #pragma unroll
                for (int wp = 0; wp < 8; wp++)
                    fma2(acc2[rr][wp], w2, e2[wp]);
            }
        }
        #pragma unroll
        for (int o = 16; o; o >>= 1)
            #pragma unroll
            for (int rr = 0; rr < 4; rr++)
                #pragma unroll
                for (int wp = 0; wp < 8; wp++)
                    acc2[rr][wp] = add2(acc2[rr][wp], __shfl_xor_sync(FULLM, acc2[rr][wp], o));
        int lrr = lane >> 3, lwp = lane & 7;
        ull v = 0ULL;
        #pragma unroll
        for (int rr = 0; rr < 4; rr++)
            #pragma unroll
            for (int wp = 0; wp < 8; wp++)
                if (rr == lrr && wp == lwp) v = acc2[rr][wp];
        int r = w*4 + lrr;
        float bias_r = e2rb[r];
        float lo, hi; unpack2(v, lo, hi);
        float s0, c0, s1, c1;
        sincosf((lo + bias_r)*0.5f, &s0, &c0);
        sincosf((hi + bias_r)*0.5f, &s1, &c1);
        sh_ang[2*lwp][r]     = make_float2(c0, s0);
        sh_ang[2*lwp + 1][r] = make_float2(c1, s1);
    }
    __syncthreads();

    float2 pacc = make_float2((t == 0) ? poly[0] : 0.f, 0.f);

    #pragma unroll 1
    for (int d = 1; d <= 3; d++){
        float2 s[8];
        if (d == 1){
            #pragma unroll
            for (int r = 0; r < 8; r++)
                s[r] = make_float2((lane == 0 && r == 0) ? 1.f : 0.f, 0.f);
        } else {
            #pragma unroll
            for (int r = 0; r < 8; r++) s[r] = sh_comb[lane*8 + r];
        }
        #pragma unroll 1
        for (int l = 0; l < 2; l++)
            layer(s, &sh_ang[w][32*l], lane);
        #pragma unroll
        for (int r = 0; r < 8; r++) u.st[w][lane*8 + r] = s[r];
        __syncthreads();
        if (t < DIM){
            float2 acc2 = make_float2(0.f, 0.f);
            #pragma unroll
            for (int ww = 0; ww < NW; ww++){
                float2 c = sh_cf[ww];
                float2 v = u.st[ww][t];
                acc2.x += c.x*v.x - c.y*v.y;
                acc2.y += c.x*v.y + c.y*v.x;
            }
            float pd = poly[d];
            pacc.x += pd*acc2.x; pacc.y += pd*acc2.y;
            sh_comb[t] = acc2;
        }
        __syncthreads();
    }

    float psum = fabsf(poly[0]) + fabsf(poly[1]) + fabsf(poly[2]) + fabsf(poly[3]);
    float invp = 1.f / psum;
    float2 m = make_float2(pacc.x*invp, pacc.y*invp);
    if (t < DIM){
        float loc = m.x*m.x + m.y*m.y;
        #pragma unroll
        for (int o = 16; o; o >>= 1) loc += __shfl_xor_sync(FULLM, loc, o);
        if (lane == 0) redv[w] = loc;
    }
    __syncthreads();
    if (t == 0){
        float fp = sqrtf(redv[0]+redv[1]+redv[2]+redv[3]+redv[4]+redv[5]+redv[6]+redv[7]);
        g_fp[b] = fp;
        sh_inv = 1.f / fmaxf(fp, 1e-12f);
    }
    __syncthreads();
    if (t < DIM) sh_comb[t] = make_float2(m.x*sh_inv, m.y*sh_inv);
    __syncthreads();

    if (w == 0){
        float2 s[8];
        #pragma unroll
        for (int r = 0; r < 8; r++) s[r] = sh_comb[lane*8 + r];
        layer(s, sh_qang, lane);
        #pragma unroll
        for (int r = 0; r < 8; r++) sh_comb[lane*8 + r] = s[r];
    }
    __syncthreads();

    for (int wq = 0; wq < 8; wq++){
        int p = 7 - wq;
        if (t < 128){
            int i0 = ((t >> p) << (p+1)) | (t & ((1 << p) - 1));
            int i1 = i0 | (1 << p);
            float2 a0 = sh_comb[i0], a1 = sh_comb[i1];
            float cr = a0.x*a1.x + a0.y*a1.y;
            float ci = a0.x*a1.y - a0.y*a1.x;
            float zz = (a0.x*a0.x + a0.y*a0.y) - (a1.x*a1.x + a1.y*a1.y);
            #pragma unroll
            for (int o = 16; o; o >>= 1){
                cr += __shfl_xor_sync(FULLM, cr, o);
                ci += __shfl_xor_sync(FULLM, ci, o);
                zz += __shfl_xor_sync(FULLM, zz, o);
            }
            if (lane == 0){ red3[w*3] = cr; red3[w*3+1] = ci; red3[w*3+2] = zz; }
        }
        __syncthreads();
        if (t == 0){
            exps[wq]      = 2.f*(red3[0] + red3[3] + red3[6] + red3[9]);
            exps[8 + wq]  = 2.f*(red3[1] + red3[4] + red3[7] + red3[10]);
            exps[16 + wq] =      red3[2] + red3[5] + red3[8] + red3[11];
        }
        __syncthreads();
    }

    {
        float a = ff1b[t];
        const float* wr = ff1W + t*24;
        #pragma unroll
        for (int m2 = 0; m2 < 24; m2++) a += exps[m2] * wr[m2];
        g_h[b*EMB + t] = fmaxf(a, 0.f);
    }
}

// =====================================================================
// Kernel 2: FF2 via mma.sync m16n8k8 tf32. STATIC smem (48 KB exactly),
// no cudaFuncSetAttribute, no dynamic smem, no static guards.
// Block 256 thr (8 warps), tile 128v x 16b; warp tile 16v x 16b, full K.
// Pair layout: for k8-group g, logical (p = k&3, e = k>=4) stored at
// offset ((p + g)&3)*2 + e  -> fragment load = one conflict-free LDS.64.
// =====================================================================
__global__ void __launch_bounds__(256) ff2_mma_kernel(const float* __restrict__ W,
                                                      const float* __restrict__ bias,
                                                      float* __restrict__ out,
                                                      int write_scalar){
    __shared__ __align__(16) float hsm[8192];   // 32 KB: pair-permuted h
    __shared__ __align__(16) float wsm[4096];   // 16 KB: one W k-chunk (32 k)

    int t = threadIdx.x;
    int w = t >> 5, lane = t & 31;
    int gid = lane >> 2, tg = lane & 3;
    int v0 = blockIdx.x * 128;

    // ---- stage h once, pair-permuted: addr = (b*64 + G)*8 + ((p+G)&3)*2 + e
    {
        const float4* h4p = (const float4*)g_h;
        #pragma unroll
        for (int j = 0; j < 8; j++){
            int i = t + j*256;            // 0..2047
            float4 v = h4p[i];
            int b_ = i >> 7;
            int jj = i & 127;             // float4 within row
            int G = jj >> 1, e = jj & 1;
            int base = (b_*64 + G)*8 + e;
            hsm[base + (((0 + G)&3) << 1)] = tf32c(v.x);
            hsm[base + (((1 + G)&3) << 1)] = tf32c(v.y);
            hsm[base + (((2 + G)&3) << 1)] = tf32c(v.z);
            hsm[base + (((3 + G)&3) << 1)] = tf32c(v.w);
        }
    }
    if (write_scalar && blockIdx.x == 0 && t == 0){
        float s = 0.f;
        #pragma unroll
        for (int b = 0; b < NB; b++) s += g_fp[b];
        out[NOUT_OP] = s * (1.f/16.f);
    }

    float acc0[4] = {0.f,0.f,0.f,0.f};    // batches 0..7
    float acc1[4] = {0.f,0.f,0.f,0.f};    // batches 8..15

    const float4* W4 = (const float4*)W;

    // preload chunk 0
    float4 rr[4];
    #pragma unroll
    for (int j = 0; j < 4; j++){
        int i = t + j*256;                // 0..1023
        int r = i >> 3, jq = i & 7;
        int v = v0 + r; if (v > NVOCAB-1) v = NVOCAB-1;
        rr[j] = W4[(size_t)v*128 + jq];
    }

    #pragma unroll 1
    for (int c = 0; c < 16; c++){
        __syncthreads();                  // wsm free + (c==0) hsm ready
        // STS chunk c (pair-permuted)
        #pragma unroll
        for (int j = 0; j < 4; j++){
            int i = t + j*256;
            int r = i >> 3, jq = i & 7;
            int g = jq >> 1, e = jq & 1;
            int base = (g*128 + r)*8 + e;
            wsm[base + (((0 + g)&3) << 1)] = tf32c(rr[j].x);
            wsm[base + (((1 + g)&3) << 1)] = tf32c(rr[j].y);
            wsm[base + (((2 + g)&3) << 1)] = tf32c(rr[j].z);
            wsm[base + (((3 + g)&3) << 1)] = tf32c(rr[j].w);
        }
        __syncthreads();
        // prefetch chunk c+1 (overlaps with mma below)
        if (c < 15){
            #pragma unroll
            for (int j = 0; j < 4; j++){
                int i = t + j*256;
                int r = i >> 3, jq = i & 7;
                int v = v0 + r; if (v > NVOCAB-1) v = NVOCAB-1;
                rr[j] = W4[(size_t)v*128 + (c+1)*8 + jq];
            }
        }
        // mma over the 4 k8-groups of this chunk
        #pragma unroll
        for (int g = 0; g < 4; g++){
            int G = c*4 + g;                    // global k8-group; G&3 == g
            int po = ((tg + g) & 3) << 1;       // shared pair-permute offset
            uint2 A0 = *(const uint2*)&wsm[(g*128 + w*16 + gid    )*8 + po];
            uint2 A1 = *(const uint2*)&wsm[(g*128 + w*16 + gid + 8)*8 + po];
            uint2 B0 = *(const uint2*)&hsm[((gid    )*64 + G)*8 + po];
            uint2 B1 = *(const uint2*)&hsm[((gid + 8)*64 + G)*8 + po];
            mma8(acc0, A0, A1, B0);
            mma8(acc1, A0, A1, B1);
        }
    }
    __syncthreads();

    // epilogue: restage D into wsm as [b][vloc], then coalesced store
    {
        int vl = w*16 + gid;
        wsm[(0 + 2*tg    )*128 + vl    ] = acc0[0];
        wsm[(0 + 2*tg + 1)*128 + vl    ] = acc0[1];
        wsm[(0 + 2*tg    )*128 + vl + 8] = acc0[2];
        wsm[(0 + 2*tg + 1)*128 + vl + 8] = acc0[3];
        wsm[(8 + 2*tg    )*128 + vl    ] = acc1[0];
        wsm[(8 + 2*tg + 1)*128 + vl    ] = acc1[1];
        wsm[(8 + 2*tg    )*128 + vl + 8] = acc1[2];
        wsm[(8 + 2*tg + 1)*128 + vl + 8] = acc1[3];
    }
    __syncthreads();
    {
        int vl = t & 127;
        int vg = v0 + vl;
        if (vg < NVOCAB){
            float bv = bias[vg];
            #pragma unroll
            for (int j = 0; j < 8; j++){
                int b_ = (t >> 7) + 2*j;
                out[(size_t)b_*NVOCAB + vg] = wsm[b_*128 + vl] + bv;
            }
        }
    }
}

// ---------------- launch ----------------
extern "C" void kernel_launch(void* const* d_in, const int* in_sizes, int n_in,
                              void* d_out, int out_size){
    const int*   x    = (const int*)  d_in[0];
    const float* embW = (const float*)d_in[1];
    const float* e2rW = (const float*)d_in[2];
    const float* e2rb = (const float*)d_in[3];
    const float* poly = (const float*)d_in[4];
    const float* mix  = (const float*)d_in[5];
    const float* qff  = (const float*)d_in[6];
    const float* ff1W = (const float*)d_in[7];
    const float* ff1b = (const float*)d_in[8];
    const float* ff2W = (const float*)d_in[9];
    const float* ff2b = (const float*)d_in[10];
    float* out = (float*)d_out;

    mid_kernel<<<NB, 512>>>(x, embW, e2rW, e2rb, mix, poly, qff, ff1W, ff1b);

    int ws = (out_size > NOUT_OP) ? 1 : 0;
    ff2_mma_kernel<<<(NVOCAB + 127)/128, 256>>>(ff2W, ff2b, out, ws);
}